// round 3
// baseline (speedup 1.0000x reference)
#include <cuda_runtime.h>
#include <math.h>

// ---------------------------------------------------------------------------
// AGCRN cell, B=64, N=2048, Din=2, H=64, K=3, D=16.   All fp32.
//   S  = row_softmax(relu(E E^T)) * mask   (optional renorm if normalize!=0)
//   gcn(X): Y1 = S X ; Y2 = 2 S Y1 - X ; out[n,b,o] = sum_ki xg * (sum_d E W) + E b
//   GRU combine fused into the second projection's epilogue.
// ---------------------------------------------------------------------------

#define Nn 2048
#define Dm 16
#define Bb 64
#define Cc 66
#define BC (Bb * Cc)        // 4224
#define KC (3 * Cc)         // 198
#define OG 128
#define OU 64
#define Hh 64

// scratch (allowed: __device__ globals)
__device__ float g_S [Nn * Nn];        // 16.8 MB
__device__ float g_X0[Nn * BC];        // 34.6 MB
__device__ float g_Y1[Nn * BC];
__device__ float g_Y2[Nn * BC];
__device__ float g_ZR[Nn * Bb * OG];   // 67 MB  (sigmoid gate output, [n][b][2H])

// ---------------------------------------------------------------------------
// K1: supports (one block per row n)
// ---------------------------------------------------------------------------
__device__ __forceinline__ float block_reduce(float v, float* red, int tid, bool ismax) {
    red[tid] = v;
    __syncthreads();
    for (int s = 128; s > 0; s >>= 1) {
        if (tid < s) red[tid] = ismax ? fmaxf(red[tid], red[tid + s]) : (red[tid] + red[tid + s]);
        __syncthreads();
    }
    float r = red[0];
    __syncthreads();
    return r;
}

__global__ void __launch_bounds__(256) supports_kernel(const float* __restrict__ E,
                                                       const float* __restrict__ mask,
                                                       const int* __restrict__ normp) {
    __shared__ float row[Nn];
    __shared__ float red[256];
    const int n = blockIdx.x, tid = threadIdx.x;

    float En[16];
#pragma unroll
    for (int d = 0; d < 16; d++) En[d] = E[n * 16 + d];

    for (int m = tid; m < Nn; m += 256) {
        const float4* e4 = reinterpret_cast<const float4*>(E + m * 16);
        float v = 0.f;
#pragma unroll
        for (int q = 0; q < 4; q++) {
            float4 w = e4[q];
            v += En[4 * q + 0] * w.x + En[4 * q + 1] * w.y + En[4 * q + 2] * w.z + En[4 * q + 3] * w.w;
        }
        row[m] = fmaxf(v, 0.f);
    }
    __syncthreads();

    // softmax 1
    float lm = -1e30f;
    for (int m = tid; m < Nn; m += 256) lm = fmaxf(lm, row[m]);
    float mx = block_reduce(lm, red, tid, true);
    float ls = 0.f;
    for (int m = tid; m < Nn; m += 256) { float e = expf(row[m] - mx); row[m] = e; ls += e; }
    float sum = block_reduce(ls, red, tid, false);
    float inv = 1.f / sum;
    for (int m = tid; m < Nn; m += 256) row[m] = row[m] * inv * mask[(size_t)n * Nn + m];
    __syncthreads();

    if (*normp != 0) {  // optional second softmax (not hit for this dataset, but correct)
        lm = -1e30f;
        for (int m = tid; m < Nn; m += 256) lm = fmaxf(lm, row[m]);
        mx = block_reduce(lm, red, tid, true);
        ls = 0.f;
        for (int m = tid; m < Nn; m += 256) { float e = expf(row[m] - mx); row[m] = e; ls += e; }
        sum = block_reduce(ls, red, tid, false);
        inv = 1.f / sum;
        for (int m = tid; m < Nn; m += 256) row[m] *= inv;
        __syncthreads();
    }

    for (int m = tid; m < Nn; m += 256) g_S[(size_t)n * Nn + m] = row[m];
}

// ---------------------------------------------------------------------------
// K2: pack X0[n, b*66+c] = concat(x, state)[b, n, c]
// ---------------------------------------------------------------------------
__global__ void pack_gate_kernel(const float* __restrict__ x, const float* __restrict__ st) {
    int i = blockIdx.x * 256 + threadIdx.x;
    if (i >= Nn * BC) return;
    int n = i / BC, rbc = i - n * BC;
    int b = rbc / Cc, c = rbc - b * Cc;
    float v = (c < 2) ? x[((size_t)b * Nn + n) * 2 + c]
                      : st[((size_t)b * Nn + n) * Hh + (c - 2)];
    g_X0[i] = v;
}

// candidate = concat(x, z * state), z = ZR[..., :H]
__global__ void pack_cand_kernel(const float* __restrict__ x, const float* __restrict__ st) {
    int i = blockIdx.x * 256 + threadIdx.x;
    if (i >= Nn * BC) return;
    int n = i / BC, rbc = i - n * BC;
    int b = rbc / Cc, c = rbc - b * Cc;
    float v;
    if (c < 2) {
        v = x[((size_t)b * Nn + n) * 2 + c];
    } else {
        float z = g_ZR[((size_t)n * Bb + b) * OG + (c - 2)];
        v = z * st[((size_t)b * Nn + n) * Hh + (c - 2)];
    }
    g_X0[i] = v;
}

// ---------------------------------------------------------------------------
// K3/K4: Y = A(2048x2048) @ B(2048x4224)    EPI=1: Y = 2*A@B - C
// 128x128x16 tiles, 256 threads, 8x8 per-thread, double-buffered
// ---------------------------------------------------------------------------
template <int EPI>
__global__ void __launch_bounds__(256) gemm_kernel(const float* __restrict__ A,
                                                   const float* __restrict__ B,
                                                   const float* __restrict__ C,
                                                   float* __restrict__ Y) {
    __shared__ float As[2][128 * 17];
    __shared__ float Bs[2][16 * 128];

    const int tid = threadIdx.x;
    const int tx = tid & 15, ty = tid >> 4;
    const int col0 = blockIdx.x * 128;
    const int row0 = blockIdx.y * 128;

    float acc[8][8];
#pragma unroll
    for (int i = 0; i < 8; i++)
#pragma unroll
        for (int j = 0; j < 8; j++) acc[i][j] = 0.f;

    float4 Areg[2], Breg[2];

#define GLOAD(KT)                                                                           \
    {                                                                                       \
        _Pragma("unroll") for (int s = 0; s < 2; s++) {                                     \
            int q = tid + s * 256;                                                          \
            int ar = q >> 2, ac4 = q & 3;                                                   \
            Areg[s] = *reinterpret_cast<const float4*>(A + (size_t)(row0 + ar) * Nn + (KT) * 16 + ac4 * 4); \
            int br = q >> 5, bc = q & 31;                                                   \
            Breg[s] = *reinterpret_cast<const float4*>(B + (size_t)((KT) * 16 + br) * BC + col0 + bc * 4);  \
        }                                                                                   \
    }
#define SSTORE(BUF)                                                                         \
    {                                                                                       \
        _Pragma("unroll") for (int s = 0; s < 2; s++) {                                     \
            int q = tid + s * 256;                                                          \
            int ar = q >> 2, ac4 = q & 3;                                                   \
            As[BUF][ar * 17 + ac4 * 4 + 0] = Areg[s].x;                                     \
            As[BUF][ar * 17 + ac4 * 4 + 1] = Areg[s].y;                                     \
            As[BUF][ar * 17 + ac4 * 4 + 2] = Areg[s].z;                                     \
            As[BUF][ar * 17 + ac4 * 4 + 3] = Areg[s].w;                                     \
            int br = q >> 5, bc = q & 31;                                                   \
            *reinterpret_cast<float4*>(&Bs[BUF][br * 128 + bc * 4]) = Breg[s];              \
        }                                                                                   \
    }

    GLOAD(0);
    SSTORE(0);
    __syncthreads();

    const int nk = Nn / 16;  // 128
    for (int kt = 0; kt < nk; kt++) {
        const int buf = kt & 1;
        if (kt + 1 < nk) GLOAD(kt + 1);
#pragma unroll
        for (int k = 0; k < 16; k++) {
            float a[8], b[8];
#pragma unroll
            for (int j = 0; j < 8; j++) a[j] = As[buf][(ty * 8 + j) * 17 + k];
            float4 b0 = *reinterpret_cast<const float4*>(&Bs[buf][k * 128 + tx * 8]);
            float4 b1 = *reinterpret_cast<const float4*>(&Bs[buf][k * 128 + tx * 8 + 4]);
            b[0] = b0.x; b[1] = b0.y; b[2] = b0.z; b[3] = b0.w;
            b[4] = b1.x; b[5] = b1.y; b[6] = b1.z; b[7] = b1.w;
#pragma unroll
            for (int i = 0; i < 8; i++)
#pragma unroll
                for (int j = 0; j < 8; j++) acc[i][j] += a[i] * b[j];
        }
        if (kt + 1 < nk) {
            SSTORE(buf ^ 1);
            __syncthreads();
        }
    }

#pragma unroll
    for (int i = 0; i < 8; i++) {
        size_t off = (size_t)(row0 + ty * 8 + i) * BC + col0 + tx * 8;
        float4 o0, o1;
        if (EPI == 0) {
            o0 = make_float4(acc[i][0], acc[i][1], acc[i][2], acc[i][3]);
            o1 = make_float4(acc[i][4], acc[i][5], acc[i][6], acc[i][7]);
        } else {
            float4 c0 = *reinterpret_cast<const float4*>(C + off);
            float4 c1 = *reinterpret_cast<const float4*>(C + off + 4);
            o0 = make_float4(2.f * acc[i][0] - c0.x, 2.f * acc[i][1] - c0.y,
                             2.f * acc[i][2] - c0.z, 2.f * acc[i][3] - c0.w);
            o1 = make_float4(2.f * acc[i][4] - c1.x, 2.f * acc[i][5] - c1.y,
                             2.f * acc[i][6] - c1.z, 2.f * acc[i][7] - c1.w);
        }
        *reinterpret_cast<float4*>(Y + off) = o0;
        *reinterpret_cast<float4*>(Y + off + 4) = o1;
    }
#undef GLOAD
#undef SSTORE
}

// ---------------------------------------------------------------------------
// K5: per-node projection. One block per node n.
//   w_n[ki,o] = sum_d E[n,d] W[d,ki,o]  (built in smem, TKI=33 tiles)
//   acc[b,o]  = sum_ki xg[b,ki] w_n[ki,o]     (+ bias, activation, GRU epi)
// GATE=true : ZR = sigmoid(acc + bias)                       (O = 128)
// GATE=false: out = r*state + (1-r)*tanh(acc + bias)         (O = 64)
// ---------------------------------------------------------------------------
template <int O, bool GATE>
__global__ void __launch_bounds__(256) proj_kernel(const float* __restrict__ E,
                                                   const float* __restrict__ W,
                                                   const float* __restrict__ bp,
                                                   const float* __restrict__ st,
                                                   float* __restrict__ outp) {
    constexpr int OV = O / 4;        // o-groups of 4
    constexpr int NBG = 256 / OV;    // b-groups
    constexpr int BPT = Bb / NBG;    // b per thread
    constexpr int TKI = 33;          // 198 = 6 * 33

    extern __shared__ float sm[];
    float* xg = sm;                  // [64][198]
    float* ws = sm + Bb * KC;        // [TKI][O]
    __shared__ float Esh[16];

    const int n = blockIdx.x, tid = threadIdx.x;
    const int to = tid % OV, tb = tid / OV;

    if (tid < 16) Esh[tid] = E[n * 16 + tid];

    const float* bufs[3] = {g_X0, g_Y1, g_Y2};
#pragma unroll
    for (int k = 0; k < 3; k++) {
        const float* src = bufs[k] + (size_t)n * BC;
        for (int e = tid; e < Bb * Cc; e += 256) {
            int b = e / Cc, i = e - b * Cc;
            xg[b * KC + k * Cc + i] = src[e];
        }
    }
    __syncthreads();

    float acc[BPT][4];
#pragma unroll
    for (int j = 0; j < BPT; j++)
#pragma unroll
        for (int jo = 0; jo < 4; jo++) acc[j][jo] = 0.f;

    for (int kt = 0; kt < KC; kt += TKI) {
        // build ws tile
        for (int e = tid; e < TKI * OV; e += 256) {
            int kk = e / OV, o4 = e - kk * OV;
            const float* wp = W + (size_t)(kt + kk) * O + o4 * 4;
            float4 s = make_float4(0.f, 0.f, 0.f, 0.f);
#pragma unroll
            for (int d = 0; d < 16; d++) {
                float4 w = *reinterpret_cast<const float4*>(wp + (size_t)d * KC * O);
                float ed = Esh[d];
                s.x += ed * w.x; s.y += ed * w.y; s.z += ed * w.z; s.w += ed * w.w;
            }
            *reinterpret_cast<float4*>(&ws[kk * O + o4 * 4]) = s;
        }
        __syncthreads();

        for (int kk = 0; kk < TKI; kk++) {
            float4 w0 = *reinterpret_cast<const float4*>(&ws[kk * O + to * 4]);
            float xv[BPT];
#pragma unroll
            for (int j = 0; j < BPT; j++) xv[j] = xg[(tb * BPT + j) * KC + kt + kk];
#pragma unroll
            for (int j = 0; j < BPT; j++) {
                acc[j][0] += xv[j] * w0.x;
                acc[j][1] += xv[j] * w0.y;
                acc[j][2] += xv[j] * w0.z;
                acc[j][3] += xv[j] * w0.w;
            }
        }
        __syncthreads();  // guard ws overwrite next tile
    }

    float bias[4];
#pragma unroll
    for (int jo = 0; jo < 4; jo++) {
        float s = 0.f;
#pragma unroll
        for (int d = 0; d < 16; d++) s += Esh[d] * bp[d * O + to * 4 + jo];
        bias[jo] = s;
    }

#pragma unroll
    for (int j = 0; j < BPT; j++) {
        const int b = tb * BPT + j;
        if (GATE) {
            float4 o;
            o.x = 1.f / (1.f + expf(-(acc[j][0] + bias[0])));
            o.y = 1.f / (1.f + expf(-(acc[j][1] + bias[1])));
            o.z = 1.f / (1.f + expf(-(acc[j][2] + bias[2])));
            o.w = 1.f / (1.f + expf(-(acc[j][3] + bias[3])));
            *reinterpret_cast<float4*>(&g_ZR[((size_t)n * Bb + b) * OG + to * 4]) = o;
        } else {
            float4 o;
            float vals[4];
#pragma unroll
            for (int jo = 0; jo < 4; jo++) {
                int oo = to * 4 + jo;
                float hc = tanhf(acc[j][jo] + bias[jo]);
                float r = g_ZR[((size_t)n * Bb + b) * OG + Hh + oo];
                float sv = st[((size_t)b * Nn + n) * Hh + oo];
                vals[jo] = r * sv + (1.f - r) * hc;
            }
            o = make_float4(vals[0], vals[1], vals[2], vals[3]);
            *reinterpret_cast<float4*>(&outp[((size_t)b * Nn + n) * Hh + to * 4]) = o;
        }
    }
}

// ---------------------------------------------------------------------------
extern "C" void kernel_launch(void* const* d_in, const int* in_sizes, int n_in,
                              void* d_out, int out_size) {
    const float* x    = (const float*)d_in[0];
    const float* st   = (const float*)d_in[1];
    const float* E    = (const float*)d_in[2];
    const float* mask = (const float*)d_in[3];
    const float* gW   = (const float*)d_in[4];
    const float* gb   = (const float*)d_in[5];
    const float* uW   = (const float*)d_in[6];
    const float* ub   = (const float*)d_in[7];
    const int*   normp = (const int*)d_in[8];
    float* outp = (float*)d_out;

    void *pS, *pX0, *pY1, *pY2;
    cudaGetSymbolAddress(&pS, g_S);
    cudaGetSymbolAddress(&pX0, g_X0);
    cudaGetSymbolAddress(&pY1, g_Y1);
    cudaGetSymbolAddress(&pY2, g_Y2);

    const int smem_g = (Bb * KC + 33 * OG) * 4;  // 67584
    const int smem_u = (Bb * KC + 33 * OU) * 4;  // 59136
    cudaFuncSetAttribute(proj_kernel<OG, true>, cudaFuncAttributeMaxDynamicSharedMemorySize, smem_g);
    cudaFuncSetAttribute(proj_kernel<OU, false>, cudaFuncAttributeMaxDynamicSharedMemorySize, smem_u);

    const int packBlocks = (Nn * BC + 255) / 256;
    dim3 gg(BC / 128, Nn / 128);  // (33, 16)

    // S
    supports_kernel<<<Nn, 256>>>(E, mask, normp);

    // gate GCN
    pack_gate_kernel<<<packBlocks, 256>>>(x, st);
    gemm_kernel<0><<<gg, 256>>>((const float*)pS, (const float*)pX0, nullptr, (float*)pY1);
    gemm_kernel<1><<<gg, 256>>>((const float*)pS, (const float*)pY1, (const float*)pX0, (float*)pY2);
    proj_kernel<OG, true><<<Nn, 256, smem_g>>>(E, gW, gb, nullptr, nullptr);

    // candidate GCN + GRU combine
    pack_cand_kernel<<<packBlocks, 256>>>(x, st);
    gemm_kernel<0><<<gg, 256>>>((const float*)pS, (const float*)pX0, nullptr, (float*)pY1);
    gemm_kernel<1><<<gg, 256>>>((const float*)pS, (const float*)pY1, (const float*)pX0, (float*)pY2);
    proj_kernel<OU, false><<<Nn, 256, smem_u>>>(E, uW, ub, st, outp);
}

// round 5
// speedup vs baseline: 1.3729x; 1.3729x over previous
#include <cuda_runtime.h>
#include <math.h>

// ---------------------------------------------------------------------------
// AGCRN cell, B=64, N=2048, Din=2, H=64, K=3, D=16.   All fp32.
//   S  = row_softmax(relu(E E^T)) * mask   (optional renorm if normalize!=0)
//   gcn(X): Y1 = S X ; Y2 = 2 S Y1 - X ; out[n,b,o] = sum_ki xg * (sum_d E W) + E b
//   GRU combine fused into the second projection's epilogue.
// R3: GEMM rewritten around packed fma.rn.f32x2 (FFMA2) + cp.async pipelines.
// ---------------------------------------------------------------------------

#define Nn 2048
#define Bb 64
#define Cc 66
#define BC (Bb * Cc)        // 4224
#define KC (3 * Cc)         // 198
#define OG 128
#define OU 64
#define Hh 64

// scratch (allowed: __device__ globals)
__device__ float g_S [Nn * Nn];        // 16.8 MB
__device__ float g_St[Nn * Nn];        // 16.8 MB  (S transposed, k-major for GEMM A)
__device__ float g_X0[Nn * BC];        // 34.6 MB
__device__ float g_Y1[Nn * BC];
__device__ float g_Y2[Nn * BC];
__device__ float g_ZR[Nn * Bb * OG];   // 67 MB  (sigmoid gate output, [n][b][2H])

// ---------------------------------------------------------------------------
// helpers: packed f32x2 FMA + cp.async
// ---------------------------------------------------------------------------
__device__ __forceinline__ void ffma2(unsigned long long& d, unsigned long long a,
                                      unsigned long long b) {
    asm("fma.rn.f32x2 %0, %1, %2, %0;" : "+l"(d) : "l"(a), "l"(b));
}
__device__ __forceinline__ unsigned long long dup2(float v) {
    unsigned long long r;
    unsigned int u = __float_as_uint(v);
    asm("mov.b64 %0, {%1, %1};" : "=l"(r) : "r"(u));
    return r;
}
__device__ __forceinline__ void cpa16(unsigned int dst, const float* src) {
    asm volatile("cp.async.cg.shared.global [%0], [%1], 16;" :: "r"(dst), "l"(src));
}
__device__ __forceinline__ void cpa_commit() { asm volatile("cp.async.commit_group;"); }

union F2u { unsigned long long u; float2 f; };

// ---------------------------------------------------------------------------
// K1: supports (one block per row n)
// ---------------------------------------------------------------------------
__device__ __forceinline__ float block_reduce(float v, float* red, int tid, bool ismax) {
    red[tid] = v;
    __syncthreads();
    for (int s = 128; s > 0; s >>= 1) {
        if (tid < s) red[tid] = ismax ? fmaxf(red[tid], red[tid + s]) : (red[tid] + red[tid + s]);
        __syncthreads();
    }
    float r = red[0];
    __syncthreads();
    return r;
}

__global__ void __launch_bounds__(256) supports_kernel(const float* __restrict__ E,
                                                       const float* __restrict__ mask,
                                                       const int* __restrict__ normp) {
    __shared__ float row[Nn];
    __shared__ float red[256];
    const int n = blockIdx.x, tid = threadIdx.x;

    float En[16];
#pragma unroll
    for (int d = 0; d < 16; d++) En[d] = E[n * 16 + d];

    for (int m = tid; m < Nn; m += 256) {
        const float4* e4 = reinterpret_cast<const float4*>(E + m * 16);
        float v = 0.f;
#pragma unroll
        for (int q = 0; q < 4; q++) {
            float4 w = e4[q];
            v += En[4 * q + 0] * w.x + En[4 * q + 1] * w.y + En[4 * q + 2] * w.z + En[4 * q + 3] * w.w;
        }
        row[m] = fmaxf(v, 0.f);
    }
    __syncthreads();

    float lm = -1e30f;
    for (int m = tid; m < Nn; m += 256) lm = fmaxf(lm, row[m]);
    float mx = block_reduce(lm, red, tid, true);
    float ls = 0.f;
    for (int m = tid; m < Nn; m += 256) { float e = expf(row[m] - mx); row[m] = e; ls += e; }
    float sum = block_reduce(ls, red, tid, false);
    float inv = 1.f / sum;
    for (int m = tid; m < Nn; m += 256) row[m] = row[m] * inv * mask[(size_t)n * Nn + m];
    __syncthreads();

    if (*normp != 0) {
        lm = -1e30f;
        for (int m = tid; m < Nn; m += 256) lm = fmaxf(lm, row[m]);
        mx = block_reduce(lm, red, tid, true);
        ls = 0.f;
        for (int m = tid; m < Nn; m += 256) { float e = expf(row[m] - mx); row[m] = e; ls += e; }
        sum = block_reduce(ls, red, tid, false);
        inv = 1.f / sum;
        for (int m = tid; m < Nn; m += 256) row[m] *= inv;
        __syncthreads();
    }

    for (int m = tid; m < Nn; m += 256) g_S[(size_t)n * Nn + m] = row[m];
}

// ---------------------------------------------------------------------------
// K1b: St = S^T   (32x32 tiles)
// ---------------------------------------------------------------------------
__global__ void __launch_bounds__(256) transpose_kernel() {
    __shared__ float t[32][33];
    const int bx = blockIdx.x * 32, by = blockIdx.y * 32;
    const int tx = threadIdx.x, ty = threadIdx.y;  // block (32, 8)
#pragma unroll
    for (int j = 0; j < 32; j += 8)
        t[ty + j][tx] = g_S[(size_t)(by + ty + j) * Nn + bx + tx];
    __syncthreads();
#pragma unroll
    for (int j = 0; j < 32; j += 8)
        g_St[(size_t)(bx + ty + j) * Nn + by + tx] = t[tx][ty + j];
}

// ---------------------------------------------------------------------------
// K2: pack X0[n, b*66+c] = concat(x, state)[b, n, c]
// ---------------------------------------------------------------------------
__global__ void pack_gate_kernel(const float* __restrict__ x, const float* __restrict__ st) {
    int i = blockIdx.x * 256 + threadIdx.x;
    if (i >= Nn * BC) return;
    int n = i / BC, rbc = i - n * BC;
    int b = rbc / Cc, c = rbc - b * Cc;
    float v = (c < 2) ? x[((size_t)b * Nn + n) * 2 + c]
                      : st[((size_t)b * Nn + n) * Hh + (c - 2)];
    g_X0[i] = v;
}

__global__ void pack_cand_kernel(const float* __restrict__ x, const float* __restrict__ st) {
    int i = blockIdx.x * 256 + threadIdx.x;
    if (i >= Nn * BC) return;
    int n = i / BC, rbc = i - n * BC;
    int b = rbc / Cc, c = rbc - b * Cc;
    float v;
    if (c < 2) {
        v = x[((size_t)b * Nn + n) * 2 + c];
    } else {
        float z = g_ZR[((size_t)n * Bb + b) * OG + (c - 2)];
        v = z * st[((size_t)b * Nn + n) * Hh + (c - 2)];
    }
    g_X0[i] = v;
}

// ---------------------------------------------------------------------------
// K3/K4: Y = A(2048x2048) @ B(2048x4224)    EPI=1: Y = 2*A@B - C
//   A given TRANSPOSED (At = g_St, k-major rows).
//   128x128x16 tiles, 256 threads, 8x8 per-thread via 32 packed f32x2 accs,
//   cp.async double-buffered, 2 CTAs/SM.
// ---------------------------------------------------------------------------
template <int EPI>
__global__ void __launch_bounds__(256, 2) gemm_kernel(const float* __restrict__ At,
                                                      const float* __restrict__ B,
                                                      const float* __restrict__ C,
                                                      float* __restrict__ Y) {
    __shared__ float As[2][16 * 128];
    __shared__ float Bs[2][16 * 128];

    const int tid = threadIdx.x;
    const int tx = tid & 15, ty = tid >> 4;
    const int col0 = blockIdx.x * 128;
    const int row0 = blockIdx.y * 128;

    unsigned int as_base = (unsigned int)__cvta_generic_to_shared(&As[0][0]);
    unsigned int bs_base = (unsigned int)__cvta_generic_to_shared(&Bs[0][0]);

    // per-thread load coordinates (2 float4 per operand per stage)
    const int k0 = tid >> 5, c40 = tid & 31;          // s = 0
    const int k1 = (tid + 256) >> 5, c41 = tid & 31;  // s = 1 (same c4)

    const float* srcA0 = At + (size_t)k0 * Nn + row0 + c40 * 4;
    const float* srcA1 = At + (size_t)k1 * Nn + row0 + c41 * 4;
    const float* srcB0 = B + (size_t)k0 * BC + col0 + c40 * 4;
    const float* srcB1 = B + (size_t)k1 * BC + col0 + c41 * 4;
    const unsigned int dA0 = (unsigned int)((k0 * 128 + c40 * 4) * 4);
    const unsigned int dA1 = (unsigned int)((k1 * 128 + c41 * 4) * 4);

    unsigned long long acc[8][4];
#pragma unroll
    for (int i = 0; i < 8; i++)
#pragma unroll
        for (int p = 0; p < 4; p++) acc[i][p] = 0ull;

#define ISSUE_STAGE(KT, BUF)                                                    \
    {                                                                           \
        size_t koff = (size_t)(KT) * 16;                                        \
        unsigned int sb = (BUF) * (16 * 128 * 4);                               \
        cpa16(as_base + sb + dA0, srcA0 + koff * Nn);                           \
        cpa16(as_base + sb + dA1, srcA1 + koff * Nn);                           \
        cpa16(bs_base + sb + dA0, srcB0 + koff * BC);                           \
        cpa16(bs_base + sb + dA1, srcB1 + koff * BC);                           \
        cpa_commit();                                                           \
    }

    ISSUE_STAGE(0, 0);

    const int nk = Nn / 16;  // 128
    for (int kt = 0; kt < nk; kt++) {
        const int buf = kt & 1;
        if (kt + 1 < nk) {
            ISSUE_STAGE(kt + 1, buf ^ 1);
            asm volatile("cp.async.wait_group 1;");
        } else {
            asm volatile("cp.async.wait_group 0;");
        }
        __syncthreads();

        const float* as = &As[buf][0];
        const float* bs = &Bs[buf][0];
#pragma unroll
        for (int k = 0; k < 16; k++) {
            float4 a0 = *reinterpret_cast<const float4*>(as + k * 128 + ty * 8);
            float4 a1 = *reinterpret_cast<const float4*>(as + k * 128 + ty * 8 + 4);
            ulonglong2 bq0 = *reinterpret_cast<const ulonglong2*>(bs + k * 128 + tx * 8);
            ulonglong2 bq1 = *reinterpret_cast<const ulonglong2*>(bs + k * 128 + tx * 8 + 4);
            unsigned long long ad[8];
            ad[0] = dup2(a0.x); ad[1] = dup2(a0.y); ad[2] = dup2(a0.z); ad[3] = dup2(a0.w);
            ad[4] = dup2(a1.x); ad[5] = dup2(a1.y); ad[6] = dup2(a1.z); ad[7] = dup2(a1.w);
            unsigned long long bb[4] = {bq0.x, bq0.y, bq1.x, bq1.y};
#pragma unroll
            for (int i = 0; i < 8; i++)
#pragma unroll
                for (int p = 0; p < 4; p++) ffma2(acc[i][p], ad[i], bb[p]);
        }
        __syncthreads();  // all warps done with buf before it is refilled
    }
#undef ISSUE_STAGE

#pragma unroll
    for (int i = 0; i < 8; i++) {
        size_t off = (size_t)(row0 + ty * 8 + i) * BC + col0 + tx * 8;
        float4 o0, o1;
        F2u u0, u1, u2, u3;
        u0.u = acc[i][0]; u1.u = acc[i][1]; u2.u = acc[i][2]; u3.u = acc[i][3];
        if (EPI == 0) {
            o0 = make_float4(u0.f.x, u0.f.y, u1.f.x, u1.f.y);
            o1 = make_float4(u2.f.x, u2.f.y, u3.f.x, u3.f.y);
        } else {
            float4 c0 = *reinterpret_cast<const float4*>(C + off);
            float4 c1 = *reinterpret_cast<const float4*>(C + off + 4);
            o0 = make_float4(2.f * u0.f.x - c0.x, 2.f * u0.f.y - c0.y,
                             2.f * u1.f.x - c0.z, 2.f * u1.f.y - c0.w);
            o1 = make_float4(2.f * u2.f.x - c1.x, 2.f * u2.f.y - c1.y,
                             2.f * u3.f.x - c1.z, 2.f * u3.f.y - c1.w);
        }
        *reinterpret_cast<float4*>(Y + off) = o0;
        *reinterpret_cast<float4*>(Y + off + 4) = o1;
    }
}

// ---------------------------------------------------------------------------
// K5: per-node projection. One block per node n.
//   w_n[ki,o] = sum_d E[n,d] W[d,ki,o]  (built in smem, TKI=33 tiles)
//   acc[b,o]  = sum_ki xg[b,ki] w_n[ki,o]     (+ bias, activation, GRU epi)
// ---------------------------------------------------------------------------
template <int O, bool GATE>
__global__ void __launch_bounds__(256) proj_kernel(const float* __restrict__ E,
                                                   const float* __restrict__ W,
                                                   const float* __restrict__ bp,
                                                   const float* __restrict__ st,
                                                   float* __restrict__ outp) {
    constexpr int OV = O / 4;
    constexpr int NBG = 256 / OV;
    constexpr int BPT = Bb / NBG;
    constexpr int TKI = 33;

    extern __shared__ float sm[];
    float* xg = sm;                  // [64][198]
    float* ws = sm + Bb * KC;        // [TKI][O]
    __shared__ float Esh[16];

    const int n = blockIdx.x, tid = threadIdx.x;
    const int to = tid % OV, tb = tid / OV;

    if (tid < 16) Esh[tid] = E[n * 16 + tid];

    const float* bufs[3] = {g_X0, g_Y1, g_Y2};
#pragma unroll
    for (int k = 0; k < 3; k++) {
        const float* src = bufs[k] + (size_t)n * BC;
        for (int e = tid; e < Bb * Cc; e += 256) {
            int b = e / Cc, i = e - b * Cc;
            xg[b * KC + k * Cc + i] = src[e];
        }
    }
    __syncthreads();

    float acc[BPT][4];
#pragma unroll
    for (int j = 0; j < BPT; j++)
#pragma unroll
        for (int jo = 0; jo < 4; jo++) acc[j][jo] = 0.f;

    for (int kt = 0; kt < KC; kt += TKI) {
        for (int e = tid; e < TKI * OV; e += 256) {
            int kk = e / OV, o4 = e - kk * OV;
            const float* wp = W + (size_t)(kt + kk) * O + o4 * 4;
            float4 s = make_float4(0.f, 0.f, 0.f, 0.f);
#pragma unroll
            for (int d = 0; d < 16; d++) {
                float4 w = *reinterpret_cast<const float4*>(wp + (size_t)d * KC * O);
                float ed = Esh[d];
                s.x += ed * w.x; s.y += ed * w.y; s.z += ed * w.z; s.w += ed * w.w;
            }
            *reinterpret_cast<float4*>(&ws[kk * O + o4 * 4]) = s;
        }
        __syncthreads();

        for (int kk = 0; kk < TKI; kk++) {
            float4 w0 = *reinterpret_cast<const float4*>(&ws[kk * O + to * 4]);
            float xv[BPT];
#pragma unroll
            for (int j = 0; j < BPT; j++) xv[j] = xg[(tb * BPT + j) * KC + kt + kk];
#pragma unroll
            for (int j = 0; j < BPT; j++) {
                acc[j][0] += xv[j] * w0.x;
                acc[j][1] += xv[j] * w0.y;
                acc[j][2] += xv[j] * w0.z;
                acc[j][3] += xv[j] * w0.w;
            }
        }
        __syncthreads();
    }

    float bias[4];
#pragma unroll
    for (int jo = 0; jo < 4; jo++) {
        float s = 0.f;
#pragma unroll
        for (int d = 0; d < 16; d++) s += Esh[d] * bp[d * O + to * 4 + jo];
        bias[jo] = s;
    }

#pragma unroll
    for (int j = 0; j < BPT; j++) {
        const int b = tb * BPT + j;
        if (GATE) {
            float4 o;
            o.x = 1.f / (1.f + expf(-(acc[j][0] + bias[0])));
            o.y = 1.f / (1.f + expf(-(acc[j][1] + bias[1])));
            o.z = 1.f / (1.f + expf(-(acc[j][2] + bias[2])));
            o.w = 1.f / (1.f + expf(-(acc[j][3] + bias[3])));
            *reinterpret_cast<float4*>(&g_ZR[((size_t)n * Bb + b) * OG + to * 4]) = o;
        } else {
            float vals[4];
#pragma unroll
            for (int jo = 0; jo < 4; jo++) {
                int oo = to * 4 + jo;
                float hc = tanhf(acc[j][jo] + bias[jo]);
                float r = g_ZR[((size_t)n * Bb + b) * OG + Hh + oo];
                float sv = st[((size_t)b * Nn + n) * Hh + oo];
                vals[jo] = r * sv + (1.f - r) * hc;
            }
            float4 o = make_float4(vals[0], vals[1], vals[2], vals[3]);
            *reinterpret_cast<float4*>(&outp[((size_t)b * Nn + n) * Hh + to * 4]) = o;
        }
    }
}

// ---------------------------------------------------------------------------
extern "C" void kernel_launch(void* const* d_in, const int* in_sizes, int n_in,
                              void* d_out, int out_size) {
    const float* x    = (const float*)d_in[0];
    const float* st   = (const float*)d_in[1];
    const float* E    = (const float*)d_in[2];
    const float* mask = (const float*)d_in[3];
    const float* gW   = (const float*)d_in[4];
    const float* gb   = (const float*)d_in[5];
    const float* uW   = (const float*)d_in[6];
    const float* ub   = (const float*)d_in[7];
    const int*   normp = (const int*)d_in[8];
    float* outp = (float*)d_out;

    void *pSt, *pX0, *pY1, *pY2;
    cudaGetSymbolAddress(&pSt, g_St);
    cudaGetSymbolAddress(&pX0, g_X0);
    cudaGetSymbolAddress(&pY1, g_Y1);
    cudaGetSymbolAddress(&pY2, g_Y2);

    const int smem_g = (Bb * KC + 33 * OG) * 4;  // 67584
    const int smem_u = (Bb * KC + 33 * OU) * 4;  // 59136
    cudaFuncSetAttribute(proj_kernel<OG, true>, cudaFuncAttributeMaxDynamicSharedMemorySize, smem_g);
    cudaFuncSetAttribute(proj_kernel<OU, false>, cudaFuncAttributeMaxDynamicSharedMemorySize, smem_u);

    const int packBlocks = (Nn * BC + 255) / 256;
    dim3 gg(BC / 128, Nn / 128);  // (33, 16)
    dim3 tg(Nn / 32, Nn / 32);    // transpose grid

    // S and S^T
    supports_kernel<<<Nn, 256>>>(E, mask, normp);
    transpose_kernel<<<tg, dim3(32, 8)>>>();

    // gate GCN
    pack_gate_kernel<<<packBlocks, 256>>>(x, st);
    gemm_kernel<0><<<gg, 256>>>((const float*)pSt, (const float*)pX0, nullptr, (float*)pY1);
    gemm_kernel<1><<<gg, 256>>>((const float*)pSt, (const float*)pY1, (const float*)pX0, (float*)pY2);
    proj_kernel<OG, true><<<Nn, 256, smem_g>>>(E, gW, gb, nullptr, nullptr);

    // candidate GCN + GRU combine
    pack_cand_kernel<<<packBlocks, 256>>>(x, st);
    gemm_kernel<0><<<gg, 256>>>((const float*)pSt, (const float*)pX0, nullptr, (float*)pY1);
    gemm_kernel<1><<<gg, 256>>>((const float*)pSt, (const float*)pY1, (const float*)pX0, (float*)pY2);
    proj_kernel<OU, false><<<Nn, 256, smem_u>>>(E, uW, ub, st, outp);
}

// round 6
// speedup vs baseline: 1.3734x; 1.0004x over previous
#include <cuda_runtime.h>
#include <math.h>

// ---------------------------------------------------------------------------
// AGCRN cell, B=64, N=2048, Din=2, H=64, K=3, D=16.   All fp32.
//   S  = row_softmax(relu(E E^T)) * mask   (optional renorm if normalize!=0)
//   gcn(X): Y1 = S X ; Y2 = 2 S Y1 - X ; out[n,b,o] = sum_ki xg * (sum_d E W) + E b
//   GRU combine fused into the second projection's epilogue.
// R3: GEMM rewritten around packed fma.rn.f32x2 (FFMA2) + cp.async pipelines.
// ---------------------------------------------------------------------------

#define Nn 2048
#define Bb 64
#define Cc 66
#define BC (Bb * Cc)        // 4224
#define KC (3 * Cc)         // 198
#define OG 128
#define OU 64
#define Hh 64

// scratch (allowed: __device__ globals)
__device__ float g_S [Nn * Nn];        // 16.8 MB
__device__ float g_St[Nn * Nn];        // 16.8 MB  (S transposed, k-major for GEMM A)
__device__ float g_X0[Nn * BC];        // 34.6 MB
__device__ float g_Y1[Nn * BC];
__device__ float g_Y2[Nn * BC];
__device__ float g_ZR[Nn * Bb * OG];   // 67 MB  (sigmoid gate output, [n][b][2H])

// ---------------------------------------------------------------------------
// helpers: packed f32x2 FMA + cp.async
// ---------------------------------------------------------------------------
__device__ __forceinline__ void ffma2(unsigned long long& d, unsigned long long a,
                                      unsigned long long b) {
    asm("fma.rn.f32x2 %0, %1, %2, %0;" : "+l"(d) : "l"(a), "l"(b));
}
__device__ __forceinline__ unsigned long long dup2(float v) {
    unsigned long long r;
    unsigned int u = __float_as_uint(v);
    asm("mov.b64 %0, {%1, %1};" : "=l"(r) : "r"(u));
    return r;
}
__device__ __forceinline__ void cpa16(unsigned int dst, const float* src) {
    asm volatile("cp.async.cg.shared.global [%0], [%1], 16;" :: "r"(dst), "l"(src));
}
__device__ __forceinline__ void cpa_commit() { asm volatile("cp.async.commit_group;"); }

union F2u { unsigned long long u; float2 f; };

// ---------------------------------------------------------------------------
// K1: supports (one block per row n)
// ---------------------------------------------------------------------------
__device__ __forceinline__ float block_reduce(float v, float* red, int tid, bool ismax) {
    red[tid] = v;
    __syncthreads();
    for (int s = 128; s > 0; s >>= 1) {
        if (tid < s) red[tid] = ismax ? fmaxf(red[tid], red[tid + s]) : (red[tid] + red[tid + s]);
        __syncthreads();
    }
    float r = red[0];
    __syncthreads();
    return r;
}

__global__ void __launch_bounds__(256) supports_kernel(const float* __restrict__ E,
                                                       const float* __restrict__ mask,
                                                       const int* __restrict__ normp) {
    __shared__ float row[Nn];
    __shared__ float red[256];
    const int n = blockIdx.x, tid = threadIdx.x;

    float En[16];
#pragma unroll
    for (int d = 0; d < 16; d++) En[d] = E[n * 16 + d];

    for (int m = tid; m < Nn; m += 256) {
        const float4* e4 = reinterpret_cast<const float4*>(E + m * 16);
        float v = 0.f;
#pragma unroll
        for (int q = 0; q < 4; q++) {
            float4 w = e4[q];
            v += En[4 * q + 0] * w.x + En[4 * q + 1] * w.y + En[4 * q + 2] * w.z + En[4 * q + 3] * w.w;
        }
        row[m] = fmaxf(v, 0.f);
    }
    __syncthreads();

    float lm = -1e30f;
    for (int m = tid; m < Nn; m += 256) lm = fmaxf(lm, row[m]);
    float mx = block_reduce(lm, red, tid, true);
    float ls = 0.f;
    for (int m = tid; m < Nn; m += 256) { float e = expf(row[m] - mx); row[m] = e; ls += e; }
    float sum = block_reduce(ls, red, tid, false);
    float inv = 1.f / sum;
    for (int m = tid; m < Nn; m += 256) row[m] = row[m] * inv * mask[(size_t)n * Nn + m];
    __syncthreads();

    if (*normp != 0) {
        lm = -1e30f;
        for (int m = tid; m < Nn; m += 256) lm = fmaxf(lm, row[m]);
        mx = block_reduce(lm, red, tid, true);
        ls = 0.f;
        for (int m = tid; m < Nn; m += 256) { float e = expf(row[m] - mx); row[m] = e; ls += e; }
        sum = block_reduce(ls, red, tid, false);
        inv = 1.f / sum;
        for (int m = tid; m < Nn; m += 256) row[m] *= inv;
        __syncthreads();
    }

    for (int m = tid; m < Nn; m += 256) g_S[(size_t)n * Nn + m] = row[m];
}

// ---------------------------------------------------------------------------
// K1b: St = S^T   (32x32 tiles)
// ---------------------------------------------------------------------------
__global__ void __launch_bounds__(256) transpose_kernel() {
    __shared__ float t[32][33];
    const int bx = blockIdx.x * 32, by = blockIdx.y * 32;
    const int tx = threadIdx.x, ty = threadIdx.y;  // block (32, 8)
#pragma unroll
    for (int j = 0; j < 32; j += 8)
        t[ty + j][tx] = g_S[(size_t)(by + ty + j) * Nn + bx + tx];
    __syncthreads();
#pragma unroll
    for (int j = 0; j < 32; j += 8)
        g_St[(size_t)(bx + ty + j) * Nn + by + tx] = t[tx][ty + j];
}

// ---------------------------------------------------------------------------
// K2: pack X0[n, b*66+c] = concat(x, state)[b, n, c]
// ---------------------------------------------------------------------------
__global__ void pack_gate_kernel(const float* __restrict__ x, const float* __restrict__ st) {
    int i = blockIdx.x * 256 + threadIdx.x;
    if (i >= Nn * BC) return;
    int n = i / BC, rbc = i - n * BC;
    int b = rbc / Cc, c = rbc - b * Cc;
    float v = (c < 2) ? x[((size_t)b * Nn + n) * 2 + c]
                      : st[((size_t)b * Nn + n) * Hh + (c - 2)];
    g_X0[i] = v;
}

__global__ void pack_cand_kernel(const float* __restrict__ x, const float* __restrict__ st) {
    int i = blockIdx.x * 256 + threadIdx.x;
    if (i >= Nn * BC) return;
    int n = i / BC, rbc = i - n * BC;
    int b = rbc / Cc, c = rbc - b * Cc;
    float v;
    if (c < 2) {
        v = x[((size_t)b * Nn + n) * 2 + c];
    } else {
        float z = g_ZR[((size_t)n * Bb + b) * OG + (c - 2)];
        v = z * st[((size_t)b * Nn + n) * Hh + (c - 2)];
    }
    g_X0[i] = v;
}

// ---------------------------------------------------------------------------
// K3/K4: Y = A(2048x2048) @ B(2048x4224)    EPI=1: Y = 2*A@B - C
//   A given TRANSPOSED (At = g_St, k-major rows).
//   128x128x16 tiles, 256 threads, 8x8 per-thread via 32 packed f32x2 accs,
//   cp.async double-buffered, 2 CTAs/SM.
// ---------------------------------------------------------------------------
template <int EPI>
__global__ void __launch_bounds__(256, 2) gemm_kernel(const float* __restrict__ At,
                                                      const float* __restrict__ B,
                                                      const float* __restrict__ C,
                                                      float* __restrict__ Y) {
    __shared__ float As[2][16 * 128];
    __shared__ float Bs[2][16 * 128];

    const int tid = threadIdx.x;
    const int tx = tid & 15, ty = tid >> 4;
    const int col0 = blockIdx.x * 128;
    const int row0 = blockIdx.y * 128;

    unsigned int as_base = (unsigned int)__cvta_generic_to_shared(&As[0][0]);
    unsigned int bs_base = (unsigned int)__cvta_generic_to_shared(&Bs[0][0]);

    // per-thread load coordinates (2 float4 per operand per stage)
    const int k0 = tid >> 5, c40 = tid & 31;          // s = 0
    const int k1 = (tid + 256) >> 5, c41 = tid & 31;  // s = 1 (same c4)

    const float* srcA0 = At + (size_t)k0 * Nn + row0 + c40 * 4;
    const float* srcA1 = At + (size_t)k1 * Nn + row0 + c41 * 4;
    const float* srcB0 = B + (size_t)k0 * BC + col0 + c40 * 4;
    const float* srcB1 = B + (size_t)k1 * BC + col0 + c41 * 4;
    const unsigned int dA0 = (unsigned int)((k0 * 128 + c40 * 4) * 4);
    const unsigned int dA1 = (unsigned int)((k1 * 128 + c41 * 4) * 4);

    unsigned long long acc[8][4];
#pragma unroll
    for (int i = 0; i < 8; i++)
#pragma unroll
        for (int p = 0; p < 4; p++) acc[i][p] = 0ull;

#define ISSUE_STAGE(KT, BUF)                                                    \
    {                                                                           \
        size_t koff = (size_t)(KT) * 16;                                        \
        unsigned int sb = (BUF) * (16 * 128 * 4);                               \
        cpa16(as_base + sb + dA0, srcA0 + koff * Nn);                           \
        cpa16(as_base + sb + dA1, srcA1 + koff * Nn);                           \
        cpa16(bs_base + sb + dA0, srcB0 + koff * BC);                           \
        cpa16(bs_base + sb + dA1, srcB1 + koff * BC);                           \
        cpa_commit();                                                           \
    }

    ISSUE_STAGE(0, 0);

    const int nk = Nn / 16;  // 128
    for (int kt = 0; kt < nk; kt++) {
        const int buf = kt & 1;
        if (kt + 1 < nk) {
            ISSUE_STAGE(kt + 1, buf ^ 1);
            asm volatile("cp.async.wait_group 1;");
        } else {
            asm volatile("cp.async.wait_group 0;");
        }
        __syncthreads();

        const float* as = &As[buf][0];
        const float* bs = &Bs[buf][0];
#pragma unroll
        for (int k = 0; k < 16; k++) {
            float4 a0 = *reinterpret_cast<const float4*>(as + k * 128 + ty * 8);
            float4 a1 = *reinterpret_cast<const float4*>(as + k * 128 + ty * 8 + 4);
            ulonglong2 bq0 = *reinterpret_cast<const ulonglong2*>(bs + k * 128 + tx * 8);
            ulonglong2 bq1 = *reinterpret_cast<const ulonglong2*>(bs + k * 128 + tx * 8 + 4);
            unsigned long long ad[8];
            ad[0] = dup2(a0.x); ad[1] = dup2(a0.y); ad[2] = dup2(a0.z); ad[3] = dup2(a0.w);
            ad[4] = dup2(a1.x); ad[5] = dup2(a1.y); ad[6] = dup2(a1.z); ad[7] = dup2(a1.w);
            unsigned long long bb[4] = {bq0.x, bq0.y, bq1.x, bq1.y};
#pragma unroll
            for (int i = 0; i < 8; i++)
#pragma unroll
                for (int p = 0; p < 4; p++) ffma2(acc[i][p], ad[i], bb[p]);
        }
        __syncthreads();  // all warps done with buf before it is refilled
    }
#undef ISSUE_STAGE

#pragma unroll
    for (int i = 0; i < 8; i++) {
        size_t off = (size_t)(row0 + ty * 8 + i) * BC + col0 + tx * 8;
        float4 o0, o1;
        F2u u0, u1, u2, u3;
        u0.u = acc[i][0]; u1.u = acc[i][1]; u2.u = acc[i][2]; u3.u = acc[i][3];
        if (EPI == 0) {
            o0 = make_float4(u0.f.x, u0.f.y, u1.f.x, u1.f.y);
            o1 = make_float4(u2.f.x, u2.f.y, u3.f.x, u3.f.y);
        } else {
            float4 c0 = *reinterpret_cast<const float4*>(C + off);
            float4 c1 = *reinterpret_cast<const float4*>(C + off + 4);
            o0 = make_float4(2.f * u0.f.x - c0.x, 2.f * u0.f.y - c0.y,
                             2.f * u1.f.x - c0.z, 2.f * u1.f.y - c0.w);
            o1 = make_float4(2.f * u2.f.x - c1.x, 2.f * u2.f.y - c1.y,
                             2.f * u3.f.x - c1.z, 2.f * u3.f.y - c1.w);
        }
        *reinterpret_cast<float4*>(Y + off) = o0;
        *reinterpret_cast<float4*>(Y + off + 4) = o1;
    }
}

// ---------------------------------------------------------------------------
// K5: per-node projection. One block per node n.
//   w_n[ki,o] = sum_d E[n,d] W[d,ki,o]  (built in smem, TKI=33 tiles)
//   acc[b,o]  = sum_ki xg[b,ki] w_n[ki,o]     (+ bias, activation, GRU epi)
// ---------------------------------------------------------------------------
template <int O, bool GATE>
__global__ void __launch_bounds__(256) proj_kernel(const float* __restrict__ E,
                                                   const float* __restrict__ W,
                                                   const float* __restrict__ bp,
                                                   const float* __restrict__ st,
                                                   float* __restrict__ outp) {
    constexpr int OV = O / 4;
    constexpr int NBG = 256 / OV;
    constexpr int BPT = Bb / NBG;
    constexpr int TKI = 33;

    extern __shared__ float sm[];
    float* xg = sm;                  // [64][198]
    float* ws = sm + Bb * KC;        // [TKI][O]
    __shared__ float Esh[16];

    const int n = blockIdx.x, tid = threadIdx.x;
    const int to = tid % OV, tb = tid / OV;

    if (tid < 16) Esh[tid] = E[n * 16 + tid];

    const float* bufs[3] = {g_X0, g_Y1, g_Y2};
#pragma unroll
    for (int k = 0; k < 3; k++) {
        const float* src = bufs[k] + (size_t)n * BC;
        for (int e = tid; e < Bb * Cc; e += 256) {
            int b = e / Cc, i = e - b * Cc;
            xg[b * KC + k * Cc + i] = src[e];
        }
    }
    __syncthreads();

    float acc[BPT][4];
#pragma unroll
    for (int j = 0; j < BPT; j++)
#pragma unroll
        for (int jo = 0; jo < 4; jo++) acc[j][jo] = 0.f;

    for (int kt = 0; kt < KC; kt += TKI) {
        for (int e = tid; e < TKI * OV; e += 256) {
            int kk = e / OV, o4 = e - kk * OV;
            const float* wp = W + (size_t)(kt + kk) * O + o4 * 4;
            float4 s = make_float4(0.f, 0.f, 0.f, 0.f);
#pragma unroll
            for (int d = 0; d < 16; d++) {
                float4 w = *reinterpret_cast<const float4*>(wp + (size_t)d * KC * O);
                float ed = Esh[d];
                s.x += ed * w.x; s.y += ed * w.y; s.z += ed * w.z; s.w += ed * w.w;
            }
            *reinterpret_cast<float4*>(&ws[kk * O + o4 * 4]) = s;
        }
        __syncthreads();

        for (int kk = 0; kk < TKI; kk++) {
            float4 w0 = *reinterpret_cast<const float4*>(&ws[kk * O + to * 4]);
            float xv[BPT];
#pragma unroll
            for (int j = 0; j < BPT; j++) xv[j] = xg[(tb * BPT + j) * KC + kt + kk];
#pragma unroll
            for (int j = 0; j < BPT; j++) {
                acc[j][0] += xv[j] * w0.x;
                acc[j][1] += xv[j] * w0.y;
                acc[j][2] += xv[j] * w0.z;
                acc[j][3] += xv[j] * w0.w;
            }
        }
        __syncthreads();
    }

    float bias[4];
#pragma unroll
    for (int jo = 0; jo < 4; jo++) {
        float s = 0.f;
#pragma unroll
        for (int d = 0; d < 16; d++) s += Esh[d] * bp[d * O + to * 4 + jo];
        bias[jo] = s;
    }

#pragma unroll
    for (int j = 0; j < BPT; j++) {
        const int b = tb * BPT + j;
        if (GATE) {
            float4 o;
            o.x = 1.f / (1.f + expf(-(acc[j][0] + bias[0])));
            o.y = 1.f / (1.f + expf(-(acc[j][1] + bias[1])));
            o.z = 1.f / (1.f + expf(-(acc[j][2] + bias[2])));
            o.w = 1.f / (1.f + expf(-(acc[j][3] + bias[3])));
            *reinterpret_cast<float4*>(&g_ZR[((size_t)n * Bb + b) * OG + to * 4]) = o;
        } else {
            float vals[4];
#pragma unroll
            for (int jo = 0; jo < 4; jo++) {
                int oo = to * 4 + jo;
                float hc = tanhf(acc[j][jo] + bias[jo]);
                float r = g_ZR[((size_t)n * Bb + b) * OG + Hh + oo];
                float sv = st[((size_t)b * Nn + n) * Hh + oo];
                vals[jo] = r * sv + (1.f - r) * hc;
            }
            float4 o = make_float4(vals[0], vals[1], vals[2], vals[3]);
            *reinterpret_cast<float4*>(&outp[((size_t)b * Nn + n) * Hh + to * 4]) = o;
        }
    }
}

// ---------------------------------------------------------------------------
extern "C" void kernel_launch(void* const* d_in, const int* in_sizes, int n_in,
                              void* d_out, int out_size) {
    const float* x    = (const float*)d_in[0];
    const float* st   = (const float*)d_in[1];
    const float* E    = (const float*)d_in[2];
    const float* mask = (const float*)d_in[3];
    const float* gW   = (const float*)d_in[4];
    const float* gb   = (const float*)d_in[5];
    const float* uW   = (const float*)d_in[6];
    const float* ub   = (const float*)d_in[7];
    const int*   normp = (const int*)d_in[8];
    float* outp = (float*)d_out;

    void *pSt, *pX0, *pY1, *pY2;
    cudaGetSymbolAddress(&pSt, g_St);
    cudaGetSymbolAddress(&pX0, g_X0);
    cudaGetSymbolAddress(&pY1, g_Y1);
    cudaGetSymbolAddress(&pY2, g_Y2);

    const int smem_g = (Bb * KC + 33 * OG) * 4;  // 67584
    const int smem_u = (Bb * KC + 33 * OU) * 4;  // 59136
    cudaFuncSetAttribute(proj_kernel<OG, true>, cudaFuncAttributeMaxDynamicSharedMemorySize, smem_g);
    cudaFuncSetAttribute(proj_kernel<OU, false>, cudaFuncAttributeMaxDynamicSharedMemorySize, smem_u);

    const int packBlocks = (Nn * BC + 255) / 256;
    dim3 gg(BC / 128, Nn / 128);  // (33, 16)
    dim3 tg(Nn / 32, Nn / 32);    // transpose grid

    // S and S^T
    supports_kernel<<<Nn, 256>>>(E, mask, normp);
    transpose_kernel<<<tg, dim3(32, 8)>>>();

    // gate GCN
    pack_gate_kernel<<<packBlocks, 256>>>(x, st);
    gemm_kernel<0><<<gg, 256>>>((const float*)pSt, (const float*)pX0, nullptr, (float*)pY1);
    gemm_kernel<1><<<gg, 256>>>((const float*)pSt, (const float*)pY1, (const float*)pX0, (float*)pY2);
    proj_kernel<OG, true><<<Nn, 256, smem_g>>>(E, gW, gb, nullptr, nullptr);

    // candidate GCN + GRU combine
    pack_cand_kernel<<<packBlocks, 256>>>(x, st);
    gemm_kernel<0><<<gg, 256>>>((const float*)pSt, (const float*)pX0, nullptr, (float*)pY1);
    gemm_kernel<1><<<gg, 256>>>((const float*)pSt, (const float*)pY1, (const float*)pX0, (float*)pY2);
    proj_kernel<OU, false><<<Nn, 256, smem_u>>>(E, uW, ub, st, outp);
}

// round 8
// speedup vs baseline: 2.4061x; 1.7519x over previous
#include <cuda_runtime.h>
#include <cuda_bf16.h>
#include <math.h>

// ---------------------------------------------------------------------------
// AGCRN cell, B=64, N=2048, Din=2, H=64, K=3, D=16.
// R7: S@X GEMMs on mma.sync.m16n8k16 bf16 (fallback HMMA, plain sm_103-legal),
// bf16x3 split operands + fp32 accumulation. tcgen05 is unavailable in this
// build (ptxas targets sm_103, not sm_103a).
// ---------------------------------------------------------------------------

#define Nn 2048
#define Bb 64
#define Cc 66
#define BC 4224             // Bb * Cc = 33 * 128
#define KC 198              // 3 * Cc
#define OG 128
#define OU 64
#define Hh 64

#define MT 128              // GEMM m-tile (nodes)
#define NT 128              // GEMM n-tile (bc columns)
#define KT 32               // k per stage
#define NKC (Nn / KT)       // 64 stages
#define PL 10240            // bytes per smem plane: 128 rows * 80B
#define STG (4 * PL)        // 40960 bytes per pipeline stage

// scratch (__device__ globals)
__device__ __nv_bfloat16 g_Shi[(size_t)Nn * Nn];   // S hi plane (k-major rows)
__device__ __nv_bfloat16 g_Slo[(size_t)Nn * Nn];
__device__ __nv_bfloat16 g_Xth[(size_t)BC * Nn];   // X^T hi (bc-major rows)
__device__ __nv_bfloat16 g_Xtl[(size_t)BC * Nn];
__device__ __nv_bfloat16 g_Yth[(size_t)BC * Nn];   // Y1^T hi
__device__ __nv_bfloat16 g_Ytl[(size_t)BC * Nn];
__device__ float g_X0[(size_t)Nn * BC];            // node-major fp32
__device__ float g_Y1[(size_t)Nn * BC];
__device__ float g_Y2[(size_t)Nn * BC];
__device__ float g_ZR[(size_t)Bb * Nn * OG];       // gate out, [b][n][2H]

// ---------------------------------------------------------------------------
// PTX helpers (all plain-sm_103-legal: cp.async / ldmatrix / mma.sync)
// ---------------------------------------------------------------------------
__device__ __forceinline__ unsigned smem_u32(const void* p) {
    unsigned a;
    asm("{ .reg .u64 t; cvta.to.shared.u64 t, %1; cvt.u32.u64 %0, t; }" : "=r"(a) : "l"(p));
    return a;
}
__device__ __forceinline__ void cpa16(unsigned dst, const void* src) {
    asm volatile("cp.async.cg.shared.global [%0], [%1], 16;" :: "r"(dst), "l"(src));
}
__device__ __forceinline__ void ldsm4(unsigned* r, unsigned a) {
    asm volatile("ldmatrix.sync.aligned.m8n8.x4.shared.b16 {%0,%1,%2,%3}, [%4];"
                 : "=r"(r[0]), "=r"(r[1]), "=r"(r[2]), "=r"(r[3]) : "r"(a));
}
__device__ __forceinline__ void mma_bf16(float* c, const unsigned* a, const unsigned* b) {
    asm volatile(
        "mma.sync.aligned.m16n8k16.row.col.f32.bf16.bf16.f32 "
        "{%0,%1,%2,%3}, {%4,%5,%6,%7}, {%8,%9}, {%0,%1,%2,%3};"
        : "+f"(c[0]), "+f"(c[1]), "+f"(c[2]), "+f"(c[3])
        : "r"(a[0]), "r"(a[1]), "r"(a[2]), "r"(a[3]), "r"(b[0]), "r"(b[1]));
}

// ---------------------------------------------------------------------------
// K1: supports (one block per row n)  -> bf16 hi/lo planes of S
// ---------------------------------------------------------------------------
__device__ __forceinline__ float block_reduce(float v, float* red, int tid, bool ismax) {
    red[tid] = v;
    __syncthreads();
    for (int s = 128; s > 0; s >>= 1) {
        if (tid < s) red[tid] = ismax ? fmaxf(red[tid], red[tid + s]) : (red[tid] + red[tid + s]);
        __syncthreads();
    }
    float r = red[0];
    __syncthreads();
    return r;
}

__global__ void __launch_bounds__(256) supports_kernel(const float* __restrict__ E,
                                                       const float* __restrict__ mask,
                                                       const int* __restrict__ normp) {
    __shared__ float row[Nn];
    __shared__ float red[256];
    const int n = blockIdx.x, tid = threadIdx.x;

    float En[16];
#pragma unroll
    for (int d = 0; d < 16; d++) En[d] = E[n * 16 + d];

    for (int m = tid; m < Nn; m += 256) {
        const float4* e4 = reinterpret_cast<const float4*>(E + m * 16);
        float v = 0.f;
#pragma unroll
        for (int q = 0; q < 4; q++) {
            float4 w = e4[q];
            v += En[4 * q + 0] * w.x + En[4 * q + 1] * w.y + En[4 * q + 2] * w.z + En[4 * q + 3] * w.w;
        }
        row[m] = fmaxf(v, 0.f);
    }
    __syncthreads();

    float lm = -1e30f;
    for (int m = tid; m < Nn; m += 256) lm = fmaxf(lm, row[m]);
    float mx = block_reduce(lm, red, tid, true);
    float ls = 0.f;
    for (int m = tid; m < Nn; m += 256) { float e = expf(row[m] - mx); row[m] = e; ls += e; }
    float sum = block_reduce(ls, red, tid, false);
    float inv = 1.f / sum;
    for (int m = tid; m < Nn; m += 256) row[m] = row[m] * inv * mask[(size_t)n * Nn + m];
    __syncthreads();

    if (*normp != 0) {
        lm = -1e30f;
        for (int m = tid; m < Nn; m += 256) lm = fmaxf(lm, row[m]);
        mx = block_reduce(lm, red, tid, true);
        ls = 0.f;
        for (int m = tid; m < Nn; m += 256) { float e = expf(row[m] - mx); row[m] = e; ls += e; }
        sum = block_reduce(ls, red, tid, false);
        inv = 1.f / sum;
        for (int m = tid; m < Nn; m += 256) row[m] *= inv;
        __syncthreads();
    }

    for (int m = tid; m < Nn; m += 256) {
        float v = row[m];
        __nv_bfloat16 h = __float2bfloat16(v);
        g_Shi[(size_t)n * Nn + m] = h;
        g_Slo[(size_t)n * Nn + m] = __float2bfloat16(v - __bfloat162float(h));
    }
}

// ---------------------------------------------------------------------------
// K2: pack. Emits node-major fp32 X0 AND transposed bf16 hi/lo planes.
// grid (Nn/32, Bb), block 256.  CAND: concat(x, z*state), z = ZR[b][n][0:H]
// ---------------------------------------------------------------------------
template <bool CAND>
__global__ void __launch_bounds__(256) pack_kernel(const float* __restrict__ x,
                                                   const float* __restrict__ st) {
    __shared__ float s[32 * 65];
    __shared__ float z[32 * 65];
    __shared__ float xt[64];
    const int n0 = blockIdx.x * 32, b = blockIdx.y, tid = threadIdx.x;

    const float* sp = st + ((size_t)b * Nn + n0) * Hh;
#pragma unroll
    for (int j = 0; j < 8; j++) {
        int e = tid + 256 * j;
        s[(e >> 6) * 65 + (e & 63)] = sp[e];
    }
    if (tid < 64) xt[tid] = x[((size_t)b * Nn + n0 + (tid >> 1)) * 2 + (tid & 1)];
    if (CAND) {
        const float* zp = g_ZR + ((size_t)b * Nn + n0) * OG;
#pragma unroll
        for (int j = 0; j < 8; j++) {
            int e = tid + 256 * j;
            z[(e >> 6) * 65 + (e & 63)] = zp[(e >> 6) * OG + (e & 63)];
        }
    }
    __syncthreads();

    // node-major fp32
    for (int e = tid; e < 32 * Cc; e += 256) {
        int i = e / Cc, c = e - i * Cc;
        float v = (c < 2) ? xt[i * 2 + c]
                          : (CAND ? z[i * 65 + (c - 2)] * s[i * 65 + (c - 2)]
                                  : s[i * 65 + (c - 2)]);
        g_X0[(size_t)(n0 + i) * BC + b * Cc + c] = v;
    }
    // transposed bf16 planes (coalesced over n)
    for (int e = tid; e < Cc * 32; e += 256) {
        int c = e >> 5, i = e & 31;
        float v = (c < 2) ? xt[i * 2 + c]
                          : (CAND ? z[i * 65 + (c - 2)] * s[i * 65 + (c - 2)]
                                  : s[i * 65 + (c - 2)]);
        __nv_bfloat16 h = __float2bfloat16(v);
        size_t o = (size_t)(b * Cc + c) * Nn + n0 + i;
        g_Xth[o] = h;
        g_Xtl[o] = __float2bfloat16(v - __bfloat162float(h));
    }
}

// ---------------------------------------------------------------------------
// K3: warp-mma GEMM.  Y = S @ X^T-planes   (EPI=0: Y1 = acc;  EPI=1: Y2 = 2*acc - C)
// grid (BC/NT=33, Nn/MT=16), 256 threads (8 warps, 4m x 2n), 80KB dyn smem.
// smem per stage: [A_hi][A_lo][B_hi][B_lo], each 128 rows x 80B (32 bf16 + pad).
// ---------------------------------------------------------------------------
template <int EPI>
__device__ __forceinline__ void gemm_issue(unsigned smb, int tid, int row0, int col0,
                                           const __nv_bfloat16* __restrict__ Bhi,
                                           const __nv_bfloat16* __restrict__ Blo, int ch) {
    const unsigned base = smb + (unsigned)(ch & 1) * STG;
    const size_t kb = (size_t)ch * KT;
#pragma unroll
    for (int j = 0; j < 8; j++) {
        const int e = tid + (j & 1) * 256;      // 0..511 within plane
        const int r = e >> 2, c = e & 3;
        const unsigned d = base + (j >> 1) * PL + (unsigned)(r * 80 + c * 16);
        const __nv_bfloat16* g;
        switch (j >> 1) {
            case 0:  g = g_Shi + (size_t)(row0 + r) * Nn + kb + c * 8; break;
            case 1:  g = g_Slo + (size_t)(row0 + r) * Nn + kb + c * 8; break;
            case 2:  g = Bhi   + (size_t)(col0 + r) * Nn + kb + c * 8; break;
            default: g = Blo   + (size_t)(col0 + r) * Nn + kb + c * 8; break;
        }
        cpa16(d, g);
    }
    asm volatile("cp.async.commit_group;");
}

template <int EPI>
__global__ void __launch_bounds__(256, 2) mma_gemm(const __nv_bfloat16* __restrict__ Bhi,
                                                   const __nv_bfloat16* __restrict__ Blo,
                                                   const float* __restrict__ Cin,
                                                   float* __restrict__ Yout) {
    extern __shared__ char smem[];
    const unsigned smb = smem_u32(smem);
    const int tid = threadIdx.x, wid = tid >> 5, lane = tid & 31;
    const int col0 = blockIdx.x * NT;
    const int row0 = blockIdx.y * MT;
    const int wm = (wid >> 1) * 32;   // warp m offset (4 warps along m)
    const int wn = (wid & 1) * 64;    // warp n offset (2 warps along n)

    float acc[2][8][4];
#pragma unroll
    for (int f = 0; f < 2; f++)
#pragma unroll
        for (int g = 0; g < 8; g++)
#pragma unroll
            for (int q = 0; q < 4; q++) acc[f][g][q] = 0.f;

    gemm_issue<EPI>(smb, tid, row0, col0, Bhi, Blo, 0);

    // ldmatrix per-lane coordinates (constant across stages)
    const int am = wm + (lane & 15);                         // A row within tile
    const int akb = ((lane >> 4) * 8) * 2;                   // A k byte (per kstep add 32)
    const int bn = wn + ((lane >> 4) << 3) + (lane & 7);     // B row (n) within tile
    const int bkb = (((lane >> 3) & 1) * 8) * 2;             // B k byte

    for (int i = 0; i < NKC; i++) {
        if (i + 1 < NKC) {
            gemm_issue<EPI>(smb, tid, row0, col0, Bhi, Blo, i + 1);
            asm volatile("cp.async.wait_group 1;");
        } else {
            asm volatile("cp.async.wait_group 0;");
        }
        __syncthreads();

        const unsigned base = smb + (unsigned)(i & 1) * STG;
#pragma unroll
        for (int ks = 0; ks < 2; ks++) {
            unsigned Ah[2][4], Al[2][4];
#pragma unroll
            for (int f = 0; f < 2; f++) {
                const unsigned ad = base + (unsigned)((am + f * 16) * 80 + akb + ks * 32);
                ldsm4(Ah[f], ad);
                ldsm4(Al[f], ad + PL);
            }
#pragma unroll
            for (int g4 = 0; g4 < 4; g4++) {
                unsigned Bh[4], Bl[4];
                const unsigned bd = base + 2 * PL +
                                    (unsigned)((bn + g4 * 16) * 80 + bkb + ks * 32);
                ldsm4(Bh, bd);
                ldsm4(Bl, bd + PL);
#pragma unroll
                for (int f = 0; f < 2; f++) {
#pragma unroll
                    for (int h = 0; h < 2; h++) {
                        float* c = acc[f][g4 * 2 + h];
                        mma_bf16(c, Ah[f], Bh + h * 2);
                        mma_bf16(c, Ah[f], Bl + h * 2);
                        mma_bf16(c, Al[f], Bh + h * 2);
                    }
                }
            }
        }
        __syncthreads();   // all warps done with this buffer before refill
    }

#pragma unroll
    for (int f = 0; f < 2; f++) {
#pragma unroll
        for (int g = 0; g < 8; g++) {
            const int m = row0 + wm + f * 16 + (lane >> 2);
            const int n = col0 + wn + g * 8 + (lane & 3) * 2;
            const float* c = acc[f][g];
            const size_t o0 = (size_t)m * BC + n;
            const size_t o1 = (size_t)(m + 8) * BC + n;
            if (EPI == 0) {
                *reinterpret_cast<float2*>(&Yout[o0]) = make_float2(c[0], c[1]);
                *reinterpret_cast<float2*>(&Yout[o1]) = make_float2(c[2], c[3]);
            } else {
                float2 x0 = *reinterpret_cast<const float2*>(&Cin[o0]);
                float2 x1 = *reinterpret_cast<const float2*>(&Cin[o1]);
                *reinterpret_cast<float2*>(&Yout[o0]) =
                    make_float2(2.f * c[0] - x0.x, 2.f * c[1] - x0.y);
                *reinterpret_cast<float2*>(&Yout[o1]) =
                    make_float2(2.f * c[2] - x1.x, 2.f * c[3] - x1.y);
            }
        }
    }
}

// ---------------------------------------------------------------------------
// K4: transpose-split Y1 (node-major fp32) -> Y1^T hi/lo bf16 planes
// grid (BC/32=132, Nn/32=64), block (32, 8)
// ---------------------------------------------------------------------------
__global__ void __launch_bounds__(256) tsplit_kernel() {
    __shared__ float t[32][33];
    const int c0 = blockIdx.x * 32, n0 = blockIdx.y * 32;
    const int tx = threadIdx.x, ty = threadIdx.y;
#pragma unroll
    for (int j = 0; j < 32; j += 8)
        t[ty + j][tx] = g_Y1[(size_t)(n0 + ty + j) * BC + c0 + tx];
    __syncthreads();
#pragma unroll
    for (int j = 0; j < 32; j += 8) {
        float v = t[tx][ty + j];
        __nv_bfloat16 h = __float2bfloat16(v);
        size_t o = (size_t)(c0 + ty + j) * Nn + n0 + tx;
        g_Yth[o] = h;
        g_Ytl[o] = __float2bfloat16(v - __bfloat162float(h));
    }
}

// ---------------------------------------------------------------------------
// K5: per-node projection (ZR laid out [b][n][2H])
// ---------------------------------------------------------------------------
template <int O, bool GATE>
__global__ void __launch_bounds__(256) proj_kernel(const float* __restrict__ E,
                                                   const float* __restrict__ W,
                                                   const float* __restrict__ bp,
                                                   const float* __restrict__ st,
                                                   float* __restrict__ outp) {
    constexpr int OV = O / 4;
    constexpr int NBG = 256 / OV;
    constexpr int BPT = Bb / NBG;
    constexpr int TKI = 33;

    extern __shared__ float sm[];
    float* xg = sm;                  // [64][198]
    float* ws = sm + Bb * KC;        // [TKI][O]
    __shared__ float Esh[16];

    const int n = blockIdx.x, tid = threadIdx.x;
    const int to = tid % OV, tb = tid / OV;

    if (tid < 16) Esh[tid] = E[n * 16 + tid];

    const float* bufs[3] = {g_X0, g_Y1, g_Y2};
#pragma unroll
    for (int k = 0; k < 3; k++) {
        const float* src = bufs[k] + (size_t)n * BC;
        for (int e = tid; e < Bb * Cc; e += 256) {
            int b = e / Cc, i = e - b * Cc;
            xg[b * KC + k * Cc + i] = src[e];
        }
    }
    __syncthreads();

    float acc[BPT][4];
#pragma unroll
    for (int j = 0; j < BPT; j++)
#pragma unroll
        for (int jo = 0; jo < 4; jo++) acc[j][jo] = 0.f;

    for (int kt = 0; kt < KC; kt += TKI) {
        for (int e = tid; e < TKI * OV; e += 256) {
            int kk = e / OV, o4 = e - kk * OV;
            const float* wp = W + (size_t)(kt + kk) * O + o4 * 4;
            float4 s = make_float4(0.f, 0.f, 0.f, 0.f);
#pragma unroll
            for (int d = 0; d < 16; d++) {
                float4 w = *reinterpret_cast<const float4*>(wp + (size_t)d * KC * O);
                float ed = Esh[d];
                s.x += ed * w.x; s.y += ed * w.y; s.z += ed * w.z; s.w += ed * w.w;
            }
            *reinterpret_cast<float4*>(&ws[kk * O + o4 * 4]) = s;
        }
        __syncthreads();

        for (int kk = 0; kk < TKI; kk++) {
            float4 w0 = *reinterpret_cast<const float4*>(&ws[kk * O + to * 4]);
            float xv[BPT];
#pragma unroll
            for (int j = 0; j < BPT; j++) xv[j] = xg[(tb * BPT + j) * KC + kt + kk];
#pragma unroll
            for (int j = 0; j < BPT; j++) {
                acc[j][0] += xv[j] * w0.x;
                acc[j][1] += xv[j] * w0.y;
                acc[j][2] += xv[j] * w0.z;
                acc[j][3] += xv[j] * w0.w;
            }
        }
        __syncthreads();
    }

    float bias[4];
#pragma unroll
    for (int jo = 0; jo < 4; jo++) {
        float s = 0.f;
#pragma unroll
        for (int d = 0; d < 16; d++) s += Esh[d] * bp[d * O + to * 4 + jo];
        bias[jo] = s;
    }

#pragma unroll
    for (int j = 0; j < BPT; j++) {
        const int b = tb * BPT + j;
        if (GATE) {
            float4 o;
            o.x = 1.f / (1.f + expf(-(acc[j][0] + bias[0])));
            o.y = 1.f / (1.f + expf(-(acc[j][1] + bias[1])));
            o.z = 1.f / (1.f + expf(-(acc[j][2] + bias[2])));
            o.w = 1.f / (1.f + expf(-(acc[j][3] + bias[3])));
            *reinterpret_cast<float4*>(&g_ZR[((size_t)b * Nn + n) * OG + to * 4]) = o;
        } else {
            float vals[4];
#pragma unroll
            for (int jo = 0; jo < 4; jo++) {
                int oo = to * 4 + jo;
                float hc = tanhf(acc[j][jo] + bias[jo]);
                float r = g_ZR[((size_t)b * Nn + n) * OG + Hh + oo];
                float sv = st[((size_t)b * Nn + n) * Hh + oo];
                vals[jo] = r * sv + (1.f - r) * hc;
            }
            float4 o = make_float4(vals[0], vals[1], vals[2], vals[3]);
            *reinterpret_cast<float4*>(&outp[((size_t)b * Nn + n) * Hh + to * 4]) = o;
        }
    }
}

// ---------------------------------------------------------------------------
extern "C" void kernel_launch(void* const* d_in, const int* in_sizes, int n_in,
                              void* d_out, int out_size) {
    const float* x    = (const float*)d_in[0];
    const float* st   = (const float*)d_in[1];
    const float* E    = (const float*)d_in[2];
    const float* mask = (const float*)d_in[3];
    const float* gW   = (const float*)d_in[4];
    const float* gb   = (const float*)d_in[5];
    const float* uW   = (const float*)d_in[6];
    const float* ub   = (const float*)d_in[7];
    const int*   normp = (const int*)d_in[8];
    float* outp = (float*)d_out;

    void *pX0, *pY1, *pY2, *pXth, *pXtl, *pYth, *pYtl;
    cudaGetSymbolAddress(&pX0, g_X0);
    cudaGetSymbolAddress(&pY1, g_Y1);
    cudaGetSymbolAddress(&pY2, g_Y2);
    cudaGetSymbolAddress(&pXth, g_Xth);
    cudaGetSymbolAddress(&pXtl, g_Xtl);
    cudaGetSymbolAddress(&pYth, g_Yth);
    cudaGetSymbolAddress(&pYtl, g_Ytl);

    const int smem_mma = 2 * STG;                // 81920
    cudaFuncSetAttribute(mma_gemm<0>, cudaFuncAttributeMaxDynamicSharedMemorySize, smem_mma);
    cudaFuncSetAttribute(mma_gemm<1>, cudaFuncAttributeMaxDynamicSharedMemorySize, smem_mma);

    const int smem_g = (Bb * KC + 33 * OG) * 4;  // 67584
    const int smem_u = (Bb * KC + 33 * OU) * 4;  // 59136
    cudaFuncSetAttribute(proj_kernel<OG, true>, cudaFuncAttributeMaxDynamicSharedMemorySize, smem_g);
    cudaFuncSetAttribute(proj_kernel<OU, false>, cudaFuncAttributeMaxDynamicSharedMemorySize, smem_u);

    dim3 gg(BC / NT, Nn / MT);                   // (33, 16)
    dim3 pg(Nn / 32, Bb);                        // (64, 64)
    dim3 tg(BC / 32, Nn / 32);                   // (132, 64)

    supports_kernel<<<Nn, 256>>>(E, mask, normp);

    // gate GCN
    pack_kernel<false><<<pg, 256>>>(x, st);
    mma_gemm<0><<<gg, 256, smem_mma>>>((const __nv_bfloat16*)pXth, (const __nv_bfloat16*)pXtl,
                                       nullptr, (float*)pY1);
    tsplit_kernel<<<tg, dim3(32, 8)>>>();
    mma_gemm<1><<<gg, 256, smem_mma>>>((const __nv_bfloat16*)pYth, (const __nv_bfloat16*)pYtl,
                                       (const float*)pX0, (float*)pY2);
    proj_kernel<OG, true><<<Nn, 256, smem_g>>>(E, gW, gb, nullptr, nullptr);

    // candidate GCN + GRU combine
    pack_kernel<true><<<pg, 256>>>(x, st);
    mma_gemm<0><<<gg, 256, smem_mma>>>((const __nv_bfloat16*)pXth, (const __nv_bfloat16*)pXtl,
                                       nullptr, (float*)pY1);
    tsplit_kernel<<<tg, dim3(32, 8)>>>();
    mma_gemm<1><<<gg, 256, smem_mma>>>((const __nv_bfloat16*)pYth, (const __nv_bfloat16*)pYtl,
                                       (const float*)pX0, (float*)pY2);
    proj_kernel<OU, false><<<Nn, 256, smem_u>>>(E, uW, ub, st, outp);
}